// round 15
// baseline (speedup 1.0000x reference)
#include <cuda_runtime.h>
#include <cuda_fp16.h>
#include <cstdint>

#define NBATCH 4
#define NP     4096
#define DIM    256
#define NC     5
#define NROWS  (NBATCH * NP)

#define INV_T  14.285714285714286f            /* 1/0.07 */
#define CQ     20.60992915555662f             /* log2(e)/0.07 */
#define LN2F   0.6931471805599453f

/* ---- SMEM layout (bytes) ---- */
#define SM_A     0          /* Ah: 128 rows x 512B, swizzled (64 KB) */
#define SM_B     65536      /* per-half: 4 stages x 16384 (stage = 128 rows x 128B); half1 at +65536 */
#define SM_CLS   196608     /* 4096 ints */
#define SMEM_BYTES 212992

/* ---- persistent scratch (no allocations allowed) ---- */
__device__ uint32_t g_Bh[NROWS * DIM / 2];   /* tgt hi (fp16x2-packed) */
__device__ float g_pos[NROWS];               /* exact fp32 positive logit / T */
__device__ float g_m [NROWS];
__device__ float g_s [NROWS];
__device__ int      g_hist [NBATCH][32][NC];
__device__ unsigned g_chmin[NBATCH][32][NC];

/* ================= helpers ================= */
__device__ __forceinline__ uint32_t smem_u32(const void* p) {
    uint32_t a;
    asm("{ .reg .u64 t; cvta.to.shared.u64 t, %1; cvt.u32.u64 %0, t; }" : "=r"(a) : "l"(p));
    return a;
}
__device__ __forceinline__ float ex2f(float x) {
    float y; asm("ex2.approx.ftz.f32 %0, %1;" : "=f"(y) : "f"(x)); return y;
}
__device__ __forceinline__ void cp16(uint32_t dst, const void* src) {
    asm volatile("cp.async.cg.shared.global [%0], [%1], 16;" :: "r"(dst), "l"(src));
}
#define CP_COMMIT() asm volatile("cp.async.commit_group;" ::: "memory")
#define CP_WAIT0()  asm volatile("cp.async.wait_group 0;" ::: "memory")
#define BARH(id)    asm volatile("bar.sync %0, %1;" :: "r"(id), "r"(256) : "memory")

__device__ __forceinline__ void ldsm4(uint32_t (&r)[4], uint32_t addr) {
    asm volatile("ldmatrix.sync.aligned.m8n8.x4.shared.b16 {%0,%1,%2,%3}, [%4];"
                 : "=r"(r[0]), "=r"(r[1]), "=r"(r[2]), "=r"(r[3]) : "r"(addr));
}
__device__ __forceinline__ void mma_h(float (&d)[4], const uint32_t* a, const uint32_t* b) {
    asm volatile("mma.sync.aligned.m16n8k16.row.col.f32.f16.f16.f32 "
                 "{%0,%1,%2,%3}, {%4,%5,%6,%7}, {%8,%9}, {%0,%1,%2,%3};"
                 : "+f"(d[0]), "+f"(d[1]), "+f"(d[2]), "+f"(d[3])
                 : "r"(a[0]), "r"(a[1]), "r"(a[2]), "r"(a[3]), "r"(b[0]), "r"(b[1]));
}
__device__ __forceinline__ uint32_t pkh(__half a, __half b) {
    return (uint32_t)__half_as_ushort(a) | ((uint32_t)__half_as_ushort(b) << 16);
}
__device__ __forceinline__ unsigned fkey(float x) {
    unsigned u = __float_as_uint(x);
    return (u & 0x80000000u) ? ~u : (u | 0x80000000u);
}
__device__ __forceinline__ float funkey(unsigned k) {
    unsigned u = (k & 0x80000000u) ? (k & 0x7FFFFFFFu) : ~k;
    return __uint_as_float(u);
}

/* ================= Kernel 0: tgt -> fp16 hi ================= */
__global__ __launch_bounds__(256)
void cvt_h(const float* __restrict__ tgt)
{
    int i = blockIdx.x * 256 + threadIdx.x;        /* float4 index */
    float4 v = ((const float4*)tgt)[i];
    ((uint2*)g_Bh)[i] = make_uint2(
        pkh(__float2half_rn(v.x), __float2half_rn(v.y)),
        pkh(__float2half_rn(v.z), __float2half_rn(v.w)));
}

/* ================= Kernel 1: fp16 mma GEMM + fused masked softmax =============
   Identical to the R13 passing kernel EXCEPT the prologue also computes the
   exact fp32 positive-logit dot for its 128 rows (4 threads/row, shfl-reduce).
   grid (32 M-tiles, 4 batches), 512 threads = TWO independent 8-warp halves. */
__global__ __launch_bounds__(512, 1)
void nce_gemm_mma(const float* __restrict__ src, const float* __restrict__ tgt,
                  const int* __restrict__ cls)
{
    extern __shared__ __align__(1024) char smem[];
    const uint32_t sb = smem_u32(smem);
    const int tid = threadIdx.x, lane = tid & 31, w = tid >> 5;
    const int h = w >> 3, w7 = w & 7;
    const int wm = w7 >> 2, wn = w7 & 3;
    const int tid2 = tid & 255;
    const int b = blockIdx.y, mtB = blockIdx.x;
    const int R0 = b * NP + mtB * 128;
    const float NEGINF = __int_as_float(0xff800000);
    const float POSINF = __int_as_float(0x7f800000);
    int* scls = (int*)(smem + SM_CLS);

    __shared__ int      sh_h[NC];
    __shared__ unsigned sh_mk[NC];
    if (tid < NC) { sh_h[tid] = 0; sh_mk[tid] = 0xFF800000u; /* fkey(+inf) */ }

    /* ---- B stage loader (per half, 256 threads): tile i = (ct=i>>2, kc=i&3)
       stage = 128 rows x 128B, swizzle chunk^(row&7), ring slot = i&3.       */
    auto loadB = [&](int i) {
        const int ct = i >> 2, kc = i & 3, slot = i & 3;
        const uint32_t* __restrict__ gh =
            g_Bh + (size_t)(b * NP + h * 2048 + ct * 128) * 128 + kc * 32;
        const uint32_t dbase = sb + SM_B + (uint32_t)h * 65536u + (uint32_t)slot * 16384u;
#pragma unroll
        for (int q = 0; q < 4; q++) {
            int idx = tid2 + q * 256;                /* 0..1023 */
            int n = idx >> 3, c = idx & 7;
            uint32_t dst = dbase + (uint32_t)n * 128u + (uint32_t)((c ^ (n & 7)) << 4);
            cp16(dst, gh + (size_t)n * 128 + c * 4);
        }
    };
    loadB(0); CP_COMMIT();
    loadB(1); CP_COMMIT();

    /* ---- A prologue: fp32 rows -> fp16, swizzled STS (row*512 + (c^row&7)*16) */
    {
        const float4* Ag = (const float4*)(src + (size_t)R0 * DIM);
#pragma unroll
        for (int q = 0; q < 8; q++) {
            int line = tid + q * 512;               /* 0..4095 */
            int row = line >> 5, c = line & 31;
            float4 v0 = Ag[row * 64 + c * 2];
            float4 v1 = Ag[row * 64 + c * 2 + 1];
            uint4 hh4 = make_uint4(pkh(__float2half_rn(v0.x), __float2half_rn(v0.y)),
                                   pkh(__float2half_rn(v0.z), __float2half_rn(v0.w)),
                                   pkh(__float2half_rn(v1.x), __float2half_rn(v1.y)),
                                   pkh(__float2half_rn(v1.z), __float2half_rn(v1.w)));
            *(uint4*)(smem + SM_A + row * 512 + ((c ^ (row & 7)) << 4)) = hh4;
        }
    }

    /* ---- positive-logit dot: 4 threads per row, exact fp32 ---- */
    {
        const int prow = tid >> 2, pq = tid & 3;
        const float4* sp = (const float4*)(src + (size_t)(R0 + prow) * DIM) + pq * 16;
        const float4* tp = (const float4*)(tgt + (size_t)(R0 + prow) * DIM) + pq * 16;
        float p = 0.f;
#pragma unroll
        for (int k = 0; k < 16; k++) {
            float4 a = sp[k], v = tp[k];
            p += a.x * v.x + a.y * v.y + a.z * v.z + a.w * v.w;
        }
        p += __shfl_xor_sync(0xFFFFFFFFu, p, 1);
        p += __shfl_xor_sync(0xFFFFFFFFu, p, 2);
        if (pq == 0) g_pos[R0 + prow] = p * INV_T;
    }

    /* ---- class table ---- */
#pragma unroll
    for (int q = 0; q < 2; q++)
        ((int4*)scls)[tid + q * 512] = ((const int4*)(cls + b * NP))[tid + q * 512];

    /* ---- per-lane constants ---- */
    const int la7 = lane & 7;
    const int aRowBase = wm * 64 + ((lane >> 3) & 1) * 8 + la7;    /* + mt*16 */
    const uint32_t aOff = sb + SM_A + (uint32_t)aRowBase * 512u;
    const int a7s = aRowBase & 7;
    const int aKg = lane >> 4;                                     /* k8 group */
    const int nB = wn * 32 + ((lane >> 4) & 1) * 8 + la7;          /* + p*16 */
    const uint32_t bOff = (uint32_t)nB * 128u;
    const int b7s = nB & 7;
    const int bKg = (lane >> 3) & 1;
    const uint32_t Bhalf = sb + SM_B + (uint32_t)h * 65536u;

    float m_[8], s_[8], mn_[8];
#pragma unroll
    for (int j = 0; j < 8; j++) { m_[j] = NEGINF; s_[j] = 0.f; mn_[j] = POSINF; }

    float acc[4][4][4];

    /* ---- epilogue (R13-identical): masked online update, 128-col tile ---- */
    auto epilogue = [&](int ct) {
        const int cb = h * 2048 + ct * 128 + wn * 32 + (lane & 3) * 2;
        int ccls[8];
#pragma unroll
        for (int nt = 0; nt < 4; nt++) {
            ccls[nt * 2]     = scls[cb + nt * 8];
            ccls[nt * 2 + 1] = scls[cb + nt * 8 + 1];
        }
#pragma unroll
        for (int j = 0; j < 8; j++) {
            const int mt = j >> 1, hh = j & 1;
            const int rcl = scls[mtB * 128 + wm * 64 + mt * 16 + hh * 8 + (lane >> 2)];
            float tmax = NEGINF;
#pragma unroll
            for (int nt = 0; nt < 4; nt++) {
                float l0 = acc[mt][nt][hh * 2], l1 = acc[mt][nt][hh * 2 + 1];
                if (ccls[nt * 2] != rcl)     { mn_[j] = fminf(mn_[j], l0); tmax = fmaxf(tmax, l0); }
                if (ccls[nt * 2 + 1] != rcl) { mn_[j] = fminf(mn_[j], l1); tmax = fmaxf(tmax, l1); }
            }
            if (tmax != NEGINF) {
                float nm = fmaxf(m_[j], tmax * CQ);
                float a0 = 0.f, a1 = 0.f;
#pragma unroll
                for (int nt = 0; nt < 4; nt++) {
                    float l0 = acc[mt][nt][hh * 2], l1 = acc[mt][nt][hh * 2 + 1];
                    a0 += ex2f((ccls[nt * 2] != rcl)     ? l0 * CQ - nm : NEGINF);
                    a1 += ex2f((ccls[nt * 2 + 1] != rcl) ? l1 * CQ - nm : NEGINF);
                }
                s_[j] = s_[j] * ex2f(m_[j] - nm) + a0 + a1;
                m_[j] = nm;
            }
        }
    };

    /* initial: A + cls + stages 0,1 of both halves complete and visible */
    CP_WAIT0();
    __syncthreads();

#pragma unroll 1
    for (int i = 0; i < 64; i++) {
        if (i & 1) {                 /* per-half barrier at odd iterations */
            CP_WAIT0();
            BARH(h + 1);
        }
        if (i < 62) { loadB(i + 2); CP_COMMIT(); }

        const int kc = i & 3, ct = i >> 2;
        const uint32_t Bst = Bhalf + (uint32_t)(i & 3) * 16384u;
        if (kc == 0) {
#pragma unroll
            for (int mt = 0; mt < 4; mt++)
#pragma unroll
                for (int nt = 0; nt < 4; nt++)
#pragma unroll
                    for (int j = 0; j < 4; j++) acc[mt][nt][j] = 0.f;
        }

#pragma unroll
        for (int ks = 0; ks < 4; ks++) {
            uint32_t bh[2][4];
            const uint32_t cb = (uint32_t)((ks * 2 + bKg) ^ b7s) << 4;
#pragma unroll
            for (int p = 0; p < 2; p++)
                ldsm4(bh[p], Bst + bOff + (uint32_t)p * 2048u + cb);
            const uint32_t ach = (uint32_t)(kc * 8 + ks * 2 + aKg);
#pragma unroll
            for (int mt = 0; mt < 4; mt++) {
                uint32_t ah[4];
                ldsm4(ah, aOff + (uint32_t)mt * 8192u + ((ach ^ (uint32_t)a7s) << 4));
#pragma unroll
                for (int p = 0; p < 2; p++)
#pragma unroll
                    for (int hh = 0; hh < 2; hh++)
                        mma_h(acc[mt][p * 2 + hh], ah, &bh[p][hh * 2]);
            }
        }

        if (kc == 3) epilogue(ct);
    }

    /* ---- merge across the 4 lanes sharing each row (lane bits 0,1) ---- */
#pragma unroll
    for (int j = 0; j < 8; j++) {
#pragma unroll
        for (int d = 1; d <= 2; d <<= 1) {
            float om = __shfl_xor_sync(0xFFFFFFFFu, m_[j], d);
            float os = __shfl_xor_sync(0xFFFFFFFFu, s_[j], d);
            float on = __shfl_xor_sync(0xFFFFFFFFu, mn_[j], d);
            float nm = fmaxf(m_[j], om);
            float t0 = (m_[j] == NEGINF) ? 0.f : s_[j] * ex2f(m_[j] - nm);
            float t1 = (om == NEGINF) ? 0.f : os * ex2f(om - nm);
            s_[j] = t0 + t1; m_[j] = nm; mn_[j] = fminf(mn_[j], on);
        }
    }

    /* ---- cross-warp merge: 8 partials per row (4 wn x 2 halves) ---- */
    __syncthreads();
    float* mgM = (float*)(smem + SM_B);        /* [8][128] */
    float* mgS = mgM + 1024;
    float* mgN = mgS + 1024;
    if ((lane & 3) == 0) {
        const int slot = h * 4 + wn;
#pragma unroll
        for (int j = 0; j < 8; j++) {
            int row = wm * 64 + (j >> 1) * 16 + (j & 1) * 8 + (lane >> 2);
            mgM[slot * 128 + row] = m_[j];
            mgS[slot * 128 + row] = s_[j];
            mgN[slot * 128 + row] = mn_[j];
        }
    }
    __syncthreads();
    if (tid < 128) {
        float M = NEGINF, S = 0.f, MN = POSINF;
#pragma unroll
        for (int t = 0; t < 8; t++) M = fmaxf(M, mgM[t * 128 + tid]);
        if (M != NEGINF) {
#pragma unroll
            for (int t = 0; t < 8; t++) {
                float mt_ = mgM[t * 128 + tid];
                if (mt_ != NEGINF) S += mgS[t * 128 + tid] * ex2f(mt_ - M);
            }
        }
#pragma unroll
        for (int t = 0; t < 8; t++) MN = fminf(MN, mgN[t * 128 + tid]);
        g_m[R0 + tid] = M;
        g_s[R0 + tid] = S;
        /* per-chunk class histogram + class-min */
        int c = scls[mtB * 128 + tid];
        atomicAdd(&sh_h[c], 1);
        atomicMin(&sh_mk[c], fkey(MN));
    }
    __syncthreads();
    if (tid < NC) {
        g_hist [b][mtB][tid] = sh_h[tid];
        g_chmin[b][mtB][tid] = sh_mk[tid];
    }
}

/* ================= Kernel 2: final 3-way LSE + stable class-sorted scatter ===
   R13-identical (reads g_pos instead of recomputing the diagonal dot).       */
__global__ void nce_final(const int* __restrict__ cls, float* __restrict__ out)
{
    const int ch = blockIdx.x, b = blockIdx.y, tid = threadIdx.x;
    const int lane = tid & 31, w = tid >> 5;
    const int row = b * NP + ch * 128 + tid;
    const float NEGINF = __int_as_float(0xff800000);

    __shared__ int      hist_s[32][NC];
    __shared__ unsigned chm_s [32][NC];
    __shared__ int      pref_s[NC];
    __shared__ int      cnt_s [NC];
    __shared__ float    small_s[NC];
    __shared__ int      wcnt[4][NC];

    for (int i = tid; i < 32 * NC; i += 128) {
        ((int*)hist_s)[i]     = ((const int*)g_hist [b])[i];
        ((unsigned*)chm_s)[i] = ((const unsigned*)g_chmin[b])[i];
    }
    __syncthreads();
    if (tid < NC) {
        int run = 0, mypref = 0;
        unsigned mn = 0xFF800000u;
        for (int h2 = 0; h2 < 32; h2++) {
            if (h2 == ch) mypref = run;
            run += hist_s[h2][tid];
            mn = min(mn, chm_s[h2][tid]);
        }
        pref_s[tid] = mypref;
        cnt_s[tid] = run;
        small_s[tid] = fminf(funkey(mn), -10.0f) * INV_T;
    }

    const int c = cls[row];
    unsigned match = __match_any_sync(0xFFFFFFFFu, c);
    int lr = __popc(match & ((1u << lane) - 1u));
#pragma unroll
    for (int c2 = 0; c2 < NC; c2++) {
        unsigned bal = __ballot_sync(0xFFFFFFFFu, c == c2);
        if (lane == c2) wcnt[w][c2] = __popc(bal);
    }
    __syncthreads();
    for (int w2 = 0; w2 < w; w2++) lr += wcnt[w2][c];
    int classpref = 0;
    for (int c2 = 0; c2 < c; c2++) classpref += cnt_s[c2];
    const int opos = b * NP + classpref + pref_s[c] + lr;

    const float pos_n = g_pos[row];
    const float M = g_m[row], S = g_s[row];
    const float lneg = (S > 0.f) ? (M * LN2F + logf(S)) : NEGINF;

    const int   npad = cnt_s[c] - 1;
    const float pad  = (npad > 0) ? (logf((float)npad) + small_s[c]) : NEGINF;

    const float Mx  = fmaxf(pos_n, fmaxf(lneg, pad));
    const float sum = expf(pos_n - Mx) + expf(lneg - Mx) + expf(pad - Mx);
    out[opos] = Mx + logf(sum) - pos_n;
}

/* ============================================================================ */
extern "C" void kernel_launch(void* const* d_in, const int* in_sizes, int n_in,
                              void* d_out, int out_size)
{
    const float* src = (const float*)d_in[0];
    const float* tgt = (const float*)d_in[1];
    const int*   cls = (const int*)d_in[2];
    float*       out = (float*)d_out;

    cudaFuncSetAttribute(nce_gemm_mma, cudaFuncAttributeMaxDynamicSharedMemorySize, SMEM_BYTES);

    cvt_h<<<NROWS * DIM / 4 / 256, 256>>>(tgt);
    nce_gemm_mma<<<dim3(32, NBATCH), 512, SMEM_BYTES>>>(src, tgt, cls);
    nce_final<<<dim3(32, NBATCH), 128>>>(cls, out);
}

// round 16
// speedup vs baseline: 1.0430x; 1.0430x over previous
#include <cuda_runtime.h>
#include <cuda_fp16.h>
#include <cstdint>

#define NBATCH 4
#define NP     4096
#define DIM    256
#define NC     5
#define NROWS  (NBATCH * NP)

#define INV_T  14.285714285714286f            /* 1/0.07 */
#define CQ     20.60992915555662f             /* log2(e)/0.07 */
#define LN2F   0.6931471805599453f

/* ---- SMEM layout (bytes) ---- */
#define SM_A     0          /* Ah: 128 rows x 512B, swizzled (64 KB) */
#define SM_B     65536      /* per-half: 4 stages x 16384 (stage = 128 rows x 128B); half1 at +65536 */
#define SM_CLS   196608     /* 4096 ints */
#define SMEM_BYTES 212992

/* ---- persistent scratch (no allocations allowed) ---- */
__device__ uint32_t g_Bh[NROWS * DIM / 2];   /* tgt hi (fp16x2-packed) */
__device__ float g_pos[NROWS];               /* exact fp32 positive logit / T */
__device__ float g_m [NROWS];
__device__ float g_s [NROWS];
__device__ int      g_hist [NBATCH][32][NC];
__device__ unsigned g_chmin[NBATCH][32][NC];

/* ================= helpers ================= */
__device__ __forceinline__ uint32_t smem_u32(const void* p) {
    uint32_t a;
    asm("{ .reg .u64 t; cvta.to.shared.u64 t, %1; cvt.u32.u64 %0, t; }" : "=r"(a) : "l"(p));
    return a;
}
__device__ __forceinline__ float ex2f(float x) {
    float y; asm("ex2.approx.ftz.f32 %0, %1;" : "=f"(y) : "f"(x)); return y;
}
__device__ __forceinline__ void cp16(uint32_t dst, const void* src) {
    asm volatile("cp.async.cg.shared.global [%0], [%1], 16;" :: "r"(dst), "l"(src));
}
#define CP_COMMIT() asm volatile("cp.async.commit_group;" ::: "memory")
#define CP_WAIT0()  asm volatile("cp.async.wait_group 0;" ::: "memory")
#define BARH(id)    asm volatile("bar.sync %0, %1;" :: "r"(id), "r"(256) : "memory")

__device__ __forceinline__ void ldsm4(uint32_t (&r)[4], uint32_t addr) {
    asm volatile("ldmatrix.sync.aligned.m8n8.x4.shared.b16 {%0,%1,%2,%3}, [%4];"
                 : "=r"(r[0]), "=r"(r[1]), "=r"(r[2]), "=r"(r[3]) : "r"(addr));
}
__device__ __forceinline__ void mma_h(float (&d)[4], const uint32_t* a, const uint32_t* b) {
    asm volatile("mma.sync.aligned.m16n8k16.row.col.f32.f16.f16.f32 "
                 "{%0,%1,%2,%3}, {%4,%5,%6,%7}, {%8,%9}, {%0,%1,%2,%3};"
                 : "+f"(d[0]), "+f"(d[1]), "+f"(d[2]), "+f"(d[3])
                 : "r"(a[0]), "r"(a[1]), "r"(a[2]), "r"(a[3]), "r"(b[0]), "r"(b[1]));
}
__device__ __forceinline__ uint32_t pkh(__half a, __half b) {
    return (uint32_t)__half_as_ushort(a) | ((uint32_t)__half_as_ushort(b) << 16);
}
__device__ __forceinline__ unsigned fkey(float x) {
    unsigned u = __float_as_uint(x);
    return (u & 0x80000000u) ? ~u : (u | 0x80000000u);
}
__device__ __forceinline__ float funkey(unsigned k) {
    unsigned u = (k & 0x80000000u) ? (k & 0x7FFFFFFFu) : ~k;
    return __uint_as_float(u);
}

/* ================= Kernel 0: tgt -> fp16 hi + positive-logit dot =============
   8 lanes per row, 16 front-batched LDG.128 per thread (high MLP), 3-shfl
   reduction. Exact fp32 src.tgt dot, same traffic as R13, better issue rate. */
__global__ __launch_bounds__(256)
void cvt_pos(const float* __restrict__ src, const float* __restrict__ tgt)
{
    const int tid = threadIdx.x;
    const int row = blockIdx.x * 32 + (tid >> 3);
    const int seg = tid & 7;                      /* 8 segments x 32 floats */
    const float4* s4 = (const float4*)(src + (size_t)row * DIM) + seg * 8;
    const float4* t4 = (const float4*)(tgt + (size_t)row * DIM) + seg * 8;

    float4 av[8], vv[8];
#pragma unroll
    for (int j = 0; j < 8; j++) { av[j] = s4[j]; vv[j] = t4[j]; }

    float p = 0.f;
    uint2* dst = ((uint2*)g_Bh) + (size_t)row * 64 + seg * 8;
#pragma unroll
    for (int j = 0; j < 8; j++) {
        float4 a = av[j], v = vv[j];
        p += a.x * v.x + a.y * v.y + a.z * v.z + a.w * v.w;
        dst[j] = make_uint2(pkh(__float2half_rn(v.x), __float2half_rn(v.y)),
                            pkh(__float2half_rn(v.z), __float2half_rn(v.w)));
    }
    p += __shfl_xor_sync(0xFFFFFFFFu, p, 1);
    p += __shfl_xor_sync(0xFFFFFFFFu, p, 2);
    p += __shfl_xor_sync(0xFFFFFFFFu, p, 4);
    if (seg == 0) g_pos[row] = p * INV_T;
}

/* ================= Kernel 1: fp16 mma GEMM + fused masked softmax =============
   R13-identical. grid (32 M-tiles, 4 batches), 512 threads = TWO independent
   8-warp halves (own B ring + named barrier -> halves drift; epilogue overlaps
   other half's HMMA). Per half: 8 warps as 2(M) x 4(N), warp tile 64x32.     */
__global__ __launch_bounds__(512, 1)
void nce_gemm_mma(const float* __restrict__ src, const int* __restrict__ cls)
{
    extern __shared__ __align__(1024) char smem[];
    const uint32_t sb = smem_u32(smem);
    const int tid = threadIdx.x, lane = tid & 31, w = tid >> 5;
    const int h = w >> 3, w7 = w & 7;
    const int wm = w7 >> 2, wn = w7 & 3;
    const int tid2 = tid & 255;
    const int b = blockIdx.y, mtB = blockIdx.x;
    const int R0 = b * NP + mtB * 128;
    const float NEGINF = __int_as_float(0xff800000);
    const float POSINF = __int_as_float(0x7f800000);
    int* scls = (int*)(smem + SM_CLS);

    __shared__ int      sh_h[NC];
    __shared__ unsigned sh_mk[NC];
    if (tid < NC) { sh_h[tid] = 0; sh_mk[tid] = 0xFF800000u; /* fkey(+inf) */ }

    /* ---- B stage loader (per half, 256 threads): tile i = (ct=i>>2, kc=i&3)
       stage = 128 rows x 128B, swizzle chunk^(row&7), ring slot = i&3.       */
    auto loadB = [&](int i) {
        const int ct = i >> 2, kc = i & 3, slot = i & 3;
        const uint32_t* __restrict__ gh =
            g_Bh + (size_t)(b * NP + h * 2048 + ct * 128) * 128 + kc * 32;
        const uint32_t dbase = sb + SM_B + (uint32_t)h * 65536u + (uint32_t)slot * 16384u;
#pragma unroll
        for (int q = 0; q < 4; q++) {
            int idx = tid2 + q * 256;                /* 0..1023 */
            int n = idx >> 3, c = idx & 7;
            uint32_t dst = dbase + (uint32_t)n * 128u + (uint32_t)((c ^ (n & 7)) << 4);
            cp16(dst, gh + (size_t)n * 128 + c * 4);
        }
    };
    loadB(0); CP_COMMIT();
    loadB(1); CP_COMMIT();

    /* ---- A prologue: fp32 rows -> fp16, swizzled STS (row*512 + (c^row&7)*16) */
    {
        const float4* Ag = (const float4*)(src + (size_t)R0 * DIM);
#pragma unroll
        for (int q = 0; q < 8; q++) {
            int line = tid + q * 512;               /* 0..4095 */
            int row = line >> 5, c = line & 31;
            float4 v0 = Ag[row * 64 + c * 2];
            float4 v1 = Ag[row * 64 + c * 2 + 1];
            uint4 hh4 = make_uint4(pkh(__float2half_rn(v0.x), __float2half_rn(v0.y)),
                                   pkh(__float2half_rn(v0.z), __float2half_rn(v0.w)),
                                   pkh(__float2half_rn(v1.x), __float2half_rn(v1.y)),
                                   pkh(__float2half_rn(v1.z), __float2half_rn(v1.w)));
            *(uint4*)(smem + SM_A + row * 512 + ((c ^ (row & 7)) << 4)) = hh4;
        }
    }

    /* ---- class table ---- */
#pragma unroll
    for (int q = 0; q < 2; q++)
        ((int4*)scls)[tid + q * 512] = ((const int4*)(cls + b * NP))[tid + q * 512];

    /* ---- per-lane constants ---- */
    const int la7 = lane & 7;
    const int aRowBase = wm * 64 + ((lane >> 3) & 1) * 8 + la7;    /* + mt*16 */
    const uint32_t aOff = sb + SM_A + (uint32_t)aRowBase * 512u;
    const int a7s = aRowBase & 7;
    const int aKg = lane >> 4;                                     /* k8 group */
    const int nB = wn * 32 + ((lane >> 4) & 1) * 8 + la7;          /* + p*16 */
    const uint32_t bOff = (uint32_t)nB * 128u;
    const int b7s = nB & 7;
    const int bKg = (lane >> 3) & 1;
    const uint32_t Bhalf = sb + SM_B + (uint32_t)h * 65536u;

    float m_[8], s_[8], mn_[8];
#pragma unroll
    for (int j = 0; j < 8; j++) { m_[j] = NEGINF; s_[j] = 0.f; mn_[j] = POSINF; }

    float acc[4][4][4];

    /* ---- epilogue: masked online update over this half's 128-col tile ---- */
    auto epilogue = [&](int ct) {
        const int cb = h * 2048 + ct * 128 + wn * 32 + (lane & 3) * 2;
        int ccls[8];
#pragma unroll
        for (int nt = 0; nt < 4; nt++) {
            ccls[nt * 2]     = scls[cb + nt * 8];
            ccls[nt * 2 + 1] = scls[cb + nt * 8 + 1];
        }
#pragma unroll
        for (int j = 0; j < 8; j++) {
            const int mt = j >> 1, hh = j & 1;
            const int rcl = scls[mtB * 128 + wm * 64 + mt * 16 + hh * 8 + (lane >> 2)];
            float tmax = NEGINF;
#pragma unroll
            for (int nt = 0; nt < 4; nt++) {
                float l0 = acc[mt][nt][hh * 2], l1 = acc[mt][nt][hh * 2 + 1];
                if (ccls[nt * 2] != rcl)     { mn_[j] = fminf(mn_[j], l0); tmax = fmaxf(tmax, l0); }
                if (ccls[nt * 2 + 1] != rcl) { mn_[j] = fminf(mn_[j], l1); tmax = fmaxf(tmax, l1); }
            }
            if (tmax != NEGINF) {
                float nm = fmaxf(m_[j], tmax * CQ);
                float a0 = 0.f, a1 = 0.f;
#pragma unroll
                for (int nt = 0; nt < 4; nt++) {
                    float l0 = acc[mt][nt][hh * 2], l1 = acc[mt][nt][hh * 2 + 1];
                    a0 += ex2f((ccls[nt * 2] != rcl)     ? l0 * CQ - nm : NEGINF);
                    a1 += ex2f((ccls[nt * 2 + 1] != rcl) ? l1 * CQ - nm : NEGINF);
                }
                s_[j] = s_[j] * ex2f(m_[j] - nm) + a0 + a1;
                m_[j] = nm;
            }
        }
    };

    /* initial: A + cls + stages 0,1 of both halves complete and visible */
    CP_WAIT0();
    __syncthreads();

#pragma unroll 1
    for (int i = 0; i < 64; i++) {
        if (i & 1) {                 /* per-half barrier at odd iterations */
            CP_WAIT0();
            BARH(h + 1);
        }
        if (i < 62) { loadB(i + 2); CP_COMMIT(); }

        const int kc = i & 3, ct = i >> 2;
        const uint32_t Bst = Bhalf + (uint32_t)(i & 3) * 16384u;
        if (kc == 0) {
#pragma unroll
            for (int mt = 0; mt < 4; mt++)
#pragma unroll
                for (int nt = 0; nt < 4; nt++)
#pragma unroll
                    for (int j = 0; j < 4; j++) acc[mt][nt][j] = 0.f;
        }

#pragma unroll
        for (int ks = 0; ks < 4; ks++) {
            uint32_t bh[2][4];
            const uint32_t cb = (uint32_t)((ks * 2 + bKg) ^ b7s) << 4;
#pragma unroll
            for (int p = 0; p < 2; p++)
                ldsm4(bh[p], Bst + bOff + (uint32_t)p * 2048u + cb);
            const uint32_t ach = (uint32_t)(kc * 8 + ks * 2 + aKg);
#pragma unroll
            for (int mt = 0; mt < 4; mt++) {
                uint32_t ah[4];
                ldsm4(ah, aOff + (uint32_t)mt * 8192u + ((ach ^ (uint32_t)a7s) << 4));
#pragma unroll
                for (int p = 0; p < 2; p++)
#pragma unroll
                    for (int hh = 0; hh < 2; hh++)
                        mma_h(acc[mt][p * 2 + hh], ah, &bh[p][hh * 2]);
            }
        }

        if (kc == 3) epilogue(ct);
    }

    /* ---- merge across the 4 lanes sharing each row (lane bits 0,1) ---- */
#pragma unroll
    for (int j = 0; j < 8; j++) {
#pragma unroll
        for (int d = 1; d <= 2; d <<= 1) {
            float om = __shfl_xor_sync(0xFFFFFFFFu, m_[j], d);
            float os = __shfl_xor_sync(0xFFFFFFFFu, s_[j], d);
            float on = __shfl_xor_sync(0xFFFFFFFFu, mn_[j], d);
            float nm = fmaxf(m_[j], om);
            float t0 = (m_[j] == NEGINF) ? 0.f : s_[j] * ex2f(m_[j] - nm);
            float t1 = (om == NEGINF) ? 0.f : os * ex2f(om - nm);
            s_[j] = t0 + t1; m_[j] = nm; mn_[j] = fminf(mn_[j], on);
        }
    }

    /* ---- cross-warp merge: 8 partials per row (4 wn x 2 halves) ---- */
    __syncthreads();
    float* mgM = (float*)(smem + SM_B);        /* [8][128] */
    float* mgS = mgM + 1024;
    float* mgN = mgS + 1024;
    if ((lane & 3) == 0) {
        const int slot = h * 4 + wn;
#pragma unroll
        for (int j = 0; j < 8; j++) {
            int row = wm * 64 + (j >> 1) * 16 + (j & 1) * 8 + (lane >> 2);
            mgM[slot * 128 + row] = m_[j];
            mgS[slot * 128 + row] = s_[j];
            mgN[slot * 128 + row] = mn_[j];
        }
    }
    __syncthreads();
    if (tid < 128) {
        float M = NEGINF, S = 0.f, MN = POSINF;
#pragma unroll
        for (int t = 0; t < 8; t++) M = fmaxf(M, mgM[t * 128 + tid]);
        if (M != NEGINF) {
#pragma unroll
            for (int t = 0; t < 8; t++) {
                float mt_ = mgM[t * 128 + tid];
                if (mt_ != NEGINF) S += mgS[t * 128 + tid] * ex2f(mt_ - M);
            }
        }
#pragma unroll
        for (int t = 0; t < 8; t++) MN = fminf(MN, mgN[t * 128 + tid]);
        g_m[R0 + tid] = M;
        g_s[R0 + tid] = S;
        /* per-chunk class histogram + class-min */
        int c = scls[mtB * 128 + tid];
        atomicAdd(&sh_h[c], 1);
        atomicMin(&sh_mk[c], fkey(MN));
    }
    __syncthreads();
    if (tid < NC) {
        g_hist [b][mtB][tid] = sh_h[tid];
        g_chmin[b][mtB][tid] = sh_mk[tid];
    }
}

/* ================= Kernel 2: final 3-way LSE + stable class-sorted scatter ===
   R13-identical (reads g_pos from cvt_pos).                                  */
__global__ void nce_final(const int* __restrict__ cls, float* __restrict__ out)
{
    const int ch = blockIdx.x, b = blockIdx.y, tid = threadIdx.x;
    const int lane = tid & 31, w = tid >> 5;
    const int row = b * NP + ch * 128 + tid;
    const float NEGINF = __int_as_float(0xff800000);

    __shared__ int      hist_s[32][NC];
    __shared__ unsigned chm_s [32][NC];
    __shared__ int      pref_s[NC];
    __shared__ int      cnt_s [NC];
    __shared__ float    small_s[NC];
    __shared__ int      wcnt[4][NC];

    for (int i = tid; i < 32 * NC; i += 128) {
        ((int*)hist_s)[i]     = ((const int*)g_hist [b])[i];
        ((unsigned*)chm_s)[i] = ((const unsigned*)g_chmin[b])[i];
    }
    __syncthreads();
    if (tid < NC) {
        int run = 0, mypref = 0;
        unsigned mn = 0xFF800000u;
        for (int h2 = 0; h2 < 32; h2++) {
            if (h2 == ch) mypref = run;
            run += hist_s[h2][tid];
            mn = min(mn, chm_s[h2][tid]);
        }
        pref_s[tid] = mypref;
        cnt_s[tid] = run;
        small_s[tid] = fminf(funkey(mn), -10.0f) * INV_T;
    }

    const int c = cls[row];
    unsigned match = __match_any_sync(0xFFFFFFFFu, c);
    int lr = __popc(match & ((1u << lane) - 1u));
#pragma unroll
    for (int c2 = 0; c2 < NC; c2++) {
        unsigned bal = __ballot_sync(0xFFFFFFFFu, c == c2);
        if (lane == c2) wcnt[w][c2] = __popc(bal);
    }
    __syncthreads();
    for (int w2 = 0; w2 < w; w2++) lr += wcnt[w2][c];
    int classpref = 0;
    for (int c2 = 0; c2 < c; c2++) classpref += cnt_s[c2];
    const int opos = b * NP + classpref + pref_s[c] + lr;

    const float pos_n = g_pos[row];
    const float M = g_m[row], S = g_s[row];
    const float lneg = (S > 0.f) ? (M * LN2F + logf(S)) : NEGINF;

    const int   npad = cnt_s[c] - 1;
    const float pad  = (npad > 0) ? (logf((float)npad) + small_s[c]) : NEGINF;

    const float Mx  = fmaxf(pos_n, fmaxf(lneg, pad));
    const float sum = expf(pos_n - Mx) + expf(lneg - Mx) + expf(pad - Mx);
    out[opos] = Mx + logf(sum) - pos_n;
}

/* ============================================================================ */
extern "C" void kernel_launch(void* const* d_in, const int* in_sizes, int n_in,
                              void* d_out, int out_size)
{
    const float* src = (const float*)d_in[0];
    const float* tgt = (const float*)d_in[1];
    const int*   cls = (const int*)d_in[2];
    float*       out = (float*)d_out;

    cudaFuncSetAttribute(nce_gemm_mma, cudaFuncAttributeMaxDynamicSharedMemorySize, SMEM_BYTES);

    cvt_pos<<<NROWS / 32, 256>>>(src, tgt);
    nce_gemm_mma<<<dim3(32, NBATCH), 512, SMEM_BYTES>>>(src, cls);
    nce_final<<<dim3(32, NBATCH), 128>>>(cls, out);
}

// round 17
// speedup vs baseline: 1.1265x; 1.0801x over previous
#include <cuda_runtime.h>
#include <cuda_fp16.h>
#include <cstdint>

#define NBATCH 4
#define NP     4096
#define DIM    256
#define NC     5
#define NROWS  (NBATCH * NP)

#define INV_T  14.285714285714286f            /* 1/0.07 */
#define CQ     20.60992915555662f             /* log2(e)/0.07 */
#define LN2F   0.6931471805599453f

/* ---- SMEM layout (bytes) ---- */
#define SM_A     0          /* Ah: 128 rows x 512B, swizzled (64 KB) */
#define SM_B     65536      /* per-half: 4 stages x 16384 (stage = 128 rows x 128B); half1 at +65536 */
#define SM_CLS   196608     /* 4096 ints */
#define SMEM_BYTES 212992

/* ---- persistent scratch (no allocations allowed) ---- */
__device__ uint32_t g_Bh[NROWS * DIM / 2];   /* tgt hi (fp16x2-packed) */
__device__ float g_pos[NROWS];               /* exact fp32 positive logit / T */
__device__ float g_m [NROWS];
__device__ float g_s [NROWS];
__device__ int      g_hist [NBATCH][32][NC];
__device__ unsigned g_chmin[NBATCH][32][NC];

/* ================= helpers ================= */
__device__ __forceinline__ uint32_t smem_u32(const void* p) {
    uint32_t a;
    asm("{ .reg .u64 t; cvta.to.shared.u64 t, %1; cvt.u32.u64 %0, t; }" : "=r"(a) : "l"(p));
    return a;
}
__device__ __forceinline__ float ex2f(float x) {
    float y; asm("ex2.approx.ftz.f32 %0, %1;" : "=f"(y) : "f"(x)); return y;
}
__device__ __forceinline__ void cp16(uint32_t dst, const void* src) {
    asm volatile("cp.async.cg.shared.global [%0], [%1], 16;" :: "r"(dst), "l"(src));
}
#define CP_COMMIT() asm volatile("cp.async.commit_group;" ::: "memory")
#define CP_WAIT0()  asm volatile("cp.async.wait_group 0;" ::: "memory")
#define BARH(id)    asm volatile("bar.sync %0, %1;" :: "r"(id), "r"(256) : "memory")

__device__ __forceinline__ void ldsm4(uint32_t (&r)[4], uint32_t addr) {
    asm volatile("ldmatrix.sync.aligned.m8n8.x4.shared.b16 {%0,%1,%2,%3}, [%4];"
                 : "=r"(r[0]), "=r"(r[1]), "=r"(r[2]), "=r"(r[3]) : "r"(addr));
}
__device__ __forceinline__ void mma_h(float (&d)[4], const uint32_t* a, const uint32_t* b) {
    asm volatile("mma.sync.aligned.m16n8k16.row.col.f32.f16.f16.f32 "
                 "{%0,%1,%2,%3}, {%4,%5,%6,%7}, {%8,%9}, {%0,%1,%2,%3};"
                 : "+f"(d[0]), "+f"(d[1]), "+f"(d[2]), "+f"(d[3])
                 : "r"(a[0]), "r"(a[1]), "r"(a[2]), "r"(a[3]), "r"(b[0]), "r"(b[1]));
}
__device__ __forceinline__ uint32_t pkh(__half a, __half b) {
    return (uint32_t)__half_as_ushort(a) | ((uint32_t)__half_as_ushort(b) << 16);
}
__device__ __forceinline__ unsigned fkey(float x) {
    unsigned u = __float_as_uint(x);
    return (u & 0x80000000u) ? ~u : (u | 0x80000000u);
}
__device__ __forceinline__ float funkey(unsigned k) {
    unsigned u = (k & 0x80000000u) ? (k & 0x7FFFFFFFu) : ~k;
    return __uint_as_float(u);
}

/* ================= Kernel 0: tgt -> fp16 hi + positive-logit dot =============
   One warp per row (grid 2048 x 256thr, R13 geometry) with FRONT-BATCHED
   loads: all 4 LDG.128 in flight before any convert/FMA (MLP 2 -> 4).       */
__global__ __launch_bounds__(256)
void cvt_pos(const float* __restrict__ src, const float* __restrict__ tgt)
{
    const int w = threadIdx.x >> 5, lane = threadIdx.x & 31;
    const int row = blockIdx.x * 8 + w;
    const float4* s4 = (const float4*)(src + (size_t)row * DIM) + lane * 2;
    const float4* t4 = (const float4*)(tgt + (size_t)row * DIM) + lane * 2;

    float4 a0 = s4[0], a1 = s4[1];
    float4 v0 = t4[0], v1 = t4[1];

    uint2* dst = ((uint2*)g_Bh) + (size_t)row * 64 + lane * 2;
    dst[0] = make_uint2(pkh(__float2half_rn(v0.x), __float2half_rn(v0.y)),
                        pkh(__float2half_rn(v0.z), __float2half_rn(v0.w)));
    dst[1] = make_uint2(pkh(__float2half_rn(v1.x), __float2half_rn(v1.y)),
                        pkh(__float2half_rn(v1.z), __float2half_rn(v1.w)));

    float p = a0.x * v0.x + a0.y * v0.y + a0.z * v0.z + a0.w * v0.w
            + a1.x * v1.x + a1.y * v1.y + a1.z * v1.z + a1.w * v1.w;
#pragma unroll
    for (int d = 16; d > 0; d >>= 1) p += __shfl_xor_sync(0xFFFFFFFFu, p, d);
    if (lane == 0) g_pos[row] = p * INV_T;
}

/* ================= Kernel 1: fp16 mma GEMM + fused masked softmax =============
   R13-identical. grid (32 M-tiles, 4 batches), 512 threads = TWO independent
   8-warp halves (own B ring + named barrier -> halves drift; epilogue overlaps
   other half's HMMA). Per half: 8 warps as 2(M) x 4(N), warp tile 64x32.     */
__global__ __launch_bounds__(512, 1)
void nce_gemm_mma(const float* __restrict__ src, const int* __restrict__ cls)
{
    extern __shared__ __align__(1024) char smem[];
    const uint32_t sb = smem_u32(smem);
    const int tid = threadIdx.x, lane = tid & 31, w = tid >> 5;
    const int h = w >> 3, w7 = w & 7;
    const int wm = w7 >> 2, wn = w7 & 3;
    const int tid2 = tid & 255;
    const int b = blockIdx.y, mtB = blockIdx.x;
    const int R0 = b * NP + mtB * 128;
    const float NEGINF = __int_as_float(0xff800000);
    const float POSINF = __int_as_float(0x7f800000);
    int* scls = (int*)(smem + SM_CLS);

    __shared__ int      sh_h[NC];
    __shared__ unsigned sh_mk[NC];
    if (tid < NC) { sh_h[tid] = 0; sh_mk[tid] = 0xFF800000u; /* fkey(+inf) */ }

    /* ---- B stage loader (per half, 256 threads): tile i = (ct=i>>2, kc=i&3)
       stage = 128 rows x 128B, swizzle chunk^(row&7), ring slot = i&3.       */
    auto loadB = [&](int i) {
        const int ct = i >> 2, kc = i & 3, slot = i & 3;
        const uint32_t* __restrict__ gh =
            g_Bh + (size_t)(b * NP + h * 2048 + ct * 128) * 128 + kc * 32;
        const uint32_t dbase = sb + SM_B + (uint32_t)h * 65536u + (uint32_t)slot * 16384u;
#pragma unroll
        for (int q = 0; q < 4; q++) {
            int idx = tid2 + q * 256;                /* 0..1023 */
            int n = idx >> 3, c = idx & 7;
            uint32_t dst = dbase + (uint32_t)n * 128u + (uint32_t)((c ^ (n & 7)) << 4);
            cp16(dst, gh + (size_t)n * 128 + c * 4);
        }
    };
    loadB(0); CP_COMMIT();
    loadB(1); CP_COMMIT();

    /* ---- A prologue: fp32 rows -> fp16, swizzled STS (row*512 + (c^row&7)*16) */
    {
        const float4* Ag = (const float4*)(src + (size_t)R0 * DIM);
#pragma unroll
        for (int q = 0; q < 8; q++) {
            int line = tid + q * 512;               /* 0..4095 */
            int row = line >> 5, c = line & 31;
            float4 v0 = Ag[row * 64 + c * 2];
            float4 v1 = Ag[row * 64 + c * 2 + 1];
            uint4 hh4 = make_uint4(pkh(__float2half_rn(v0.x), __float2half_rn(v0.y)),
                                   pkh(__float2half_rn(v0.z), __float2half_rn(v0.w)),
                                   pkh(__float2half_rn(v1.x), __float2half_rn(v1.y)),
                                   pkh(__float2half_rn(v1.z), __float2half_rn(v1.w)));
            *(uint4*)(smem + SM_A + row * 512 + ((c ^ (row & 7)) << 4)) = hh4;
        }
    }

    /* ---- class table ---- */
#pragma unroll
    for (int q = 0; q < 2; q++)
        ((int4*)scls)[tid + q * 512] = ((const int4*)(cls + b * NP))[tid + q * 512];

    /* ---- per-lane constants ---- */
    const int la7 = lane & 7;
    const int aRowBase = wm * 64 + ((lane >> 3) & 1) * 8 + la7;    /* + mt*16 */
    const uint32_t aOff = sb + SM_A + (uint32_t)aRowBase * 512u;
    const int a7s = aRowBase & 7;
    const int aKg = lane >> 4;                                     /* k8 group */
    const int nB = wn * 32 + ((lane >> 4) & 1) * 8 + la7;          /* + p*16 */
    const uint32_t bOff = (uint32_t)nB * 128u;
    const int b7s = nB & 7;
    const int bKg = (lane >> 3) & 1;
    const uint32_t Bhalf = sb + SM_B + (uint32_t)h * 65536u;

    float m_[8], s_[8], mn_[8];
#pragma unroll
    for (int j = 0; j < 8; j++) { m_[j] = NEGINF; s_[j] = 0.f; mn_[j] = POSINF; }

    float acc[4][4][4];

    /* ---- epilogue: masked online update over this half's 128-col tile ---- */
    auto epilogue = [&](int ct) {
        const int cb = h * 2048 + ct * 128 + wn * 32 + (lane & 3) * 2;
        int ccls[8];
#pragma unroll
        for (int nt = 0; nt < 4; nt++) {
            ccls[nt * 2]     = scls[cb + nt * 8];
            ccls[nt * 2 + 1] = scls[cb + nt * 8 + 1];
        }
#pragma unroll
        for (int j = 0; j < 8; j++) {
            const int mt = j >> 1, hh = j & 1;
            const int rcl = scls[mtB * 128 + wm * 64 + mt * 16 + hh * 8 + (lane >> 2)];
            float tmax = NEGINF;
#pragma unroll
            for (int nt = 0; nt < 4; nt++) {
                float l0 = acc[mt][nt][hh * 2], l1 = acc[mt][nt][hh * 2 + 1];
                if (ccls[nt * 2] != rcl)     { mn_[j] = fminf(mn_[j], l0); tmax = fmaxf(tmax, l0); }
                if (ccls[nt * 2 + 1] != rcl) { mn_[j] = fminf(mn_[j], l1); tmax = fmaxf(tmax, l1); }
            }
            if (tmax != NEGINF) {
                float nm = fmaxf(m_[j], tmax * CQ);
                float a0 = 0.f, a1 = 0.f;
#pragma unroll
                for (int nt = 0; nt < 4; nt++) {
                    float l0 = acc[mt][nt][hh * 2], l1 = acc[mt][nt][hh * 2 + 1];
                    a0 += ex2f((ccls[nt * 2] != rcl)     ? l0 * CQ - nm : NEGINF);
                    a1 += ex2f((ccls[nt * 2 + 1] != rcl) ? l1 * CQ - nm : NEGINF);
                }
                s_[j] = s_[j] * ex2f(m_[j] - nm) + a0 + a1;
                m_[j] = nm;
            }
        }
    };

    /* initial: A + cls + stages 0,1 of both halves complete and visible */
    CP_WAIT0();
    __syncthreads();

#pragma unroll 1
    for (int i = 0; i < 64; i++) {
        if (i & 1) {                 /* per-half barrier at odd iterations */
            CP_WAIT0();
            BARH(h + 1);
        }
        if (i < 62) { loadB(i + 2); CP_COMMIT(); }

        const int kc = i & 3, ct = i >> 2;
        const uint32_t Bst = Bhalf + (uint32_t)(i & 3) * 16384u;
        if (kc == 0) {
#pragma unroll
            for (int mt = 0; mt < 4; mt++)
#pragma unroll
                for (int nt = 0; nt < 4; nt++)
#pragma unroll
                    for (int j = 0; j < 4; j++) acc[mt][nt][j] = 0.f;
        }

#pragma unroll
        for (int ks = 0; ks < 4; ks++) {
            uint32_t bh[2][4];
            const uint32_t cb = (uint32_t)((ks * 2 + bKg) ^ b7s) << 4;
#pragma unroll
            for (int p = 0; p < 2; p++)
                ldsm4(bh[p], Bst + bOff + (uint32_t)p * 2048u + cb);
            const uint32_t ach = (uint32_t)(kc * 8 + ks * 2 + aKg);
#pragma unroll
            for (int mt = 0; mt < 4; mt++) {
                uint32_t ah[4];
                ldsm4(ah, aOff + (uint32_t)mt * 8192u + ((ach ^ (uint32_t)a7s) << 4));
#pragma unroll
                for (int p = 0; p < 2; p++)
#pragma unroll
                    for (int hh = 0; hh < 2; hh++)
                        mma_h(acc[mt][p * 2 + hh], ah, &bh[p][hh * 2]);
            }
        }

        if (kc == 3) epilogue(ct);
    }

    /* ---- merge across the 4 lanes sharing each row (lane bits 0,1) ---- */
#pragma unroll
    for (int j = 0; j < 8; j++) {
#pragma unroll
        for (int d = 1; d <= 2; d <<= 1) {
            float om = __shfl_xor_sync(0xFFFFFFFFu, m_[j], d);
            float os = __shfl_xor_sync(0xFFFFFFFFu, s_[j], d);
            float on = __shfl_xor_sync(0xFFFFFFFFu, mn_[j], d);
            float nm = fmaxf(m_[j], om);
            float t0 = (m_[j] == NEGINF) ? 0.f : s_[j] * ex2f(m_[j] - nm);
            float t1 = (om == NEGINF) ? 0.f : os * ex2f(om - nm);
            s_[j] = t0 + t1; m_[j] = nm; mn_[j] = fminf(mn_[j], on);
        }
    }

    /* ---- cross-warp merge: 8 partials per row (4 wn x 2 halves) ---- */
    __syncthreads();
    float* mgM = (float*)(smem + SM_B);        /* [8][128] */
    float* mgS = mgM + 1024;
    float* mgN = mgS + 1024;
    if ((lane & 3) == 0) {
        const int slot = h * 4 + wn;
#pragma unroll
        for (int j = 0; j < 8; j++) {
            int row = wm * 64 + (j >> 1) * 16 + (j & 1) * 8 + (lane >> 2);
            mgM[slot * 128 + row] = m_[j];
            mgS[slot * 128 + row] = s_[j];
            mgN[slot * 128 + row] = mn_[j];
        }
    }
    __syncthreads();
    if (tid < 128) {
        float M = NEGINF, S = 0.f, MN = POSINF;
#pragma unroll
        for (int t = 0; t < 8; t++) M = fmaxf(M, mgM[t * 128 + tid]);
        if (M != NEGINF) {
#pragma unroll
            for (int t = 0; t < 8; t++) {
                float mt_ = mgM[t * 128 + tid];
                if (mt_ != NEGINF) S += mgS[t * 128 + tid] * ex2f(mt_ - M);
            }
        }
#pragma unroll
        for (int t = 0; t < 8; t++) MN = fminf(MN, mgN[t * 128 + tid]);
        g_m[R0 + tid] = M;
        g_s[R0 + tid] = S;
        /* per-chunk class histogram + class-min */
        int c = scls[mtB * 128 + tid];
        atomicAdd(&sh_h[c], 1);
        atomicMin(&sh_mk[c], fkey(MN));
    }
    __syncthreads();
    if (tid < NC) {
        g_hist [b][mtB][tid] = sh_h[tid];
        g_chmin[b][mtB][tid] = sh_mk[tid];
    }
}

/* ================= Kernel 2: final 3-way LSE + stable class-sorted scatter ===
   R13-identical (reads g_pos from cvt_pos).                                  */
__global__ void nce_final(const int* __restrict__ cls, float* __restrict__ out)
{
    const int ch = blockIdx.x, b = blockIdx.y, tid = threadIdx.x;
    const int lane = tid & 31, w = tid >> 5;
    const int row = b * NP + ch * 128 + tid;
    const float NEGINF = __int_as_float(0xff800000);

    __shared__ int      hist_s[32][NC];
    __shared__ unsigned chm_s [32][NC];
    __shared__ int      pref_s[NC];
    __shared__ int      cnt_s [NC];
    __shared__ float    small_s[NC];
    __shared__ int      wcnt[4][NC];

    for (int i = tid; i < 32 * NC; i += 128) {
        ((int*)hist_s)[i]     = ((const int*)g_hist [b])[i];
        ((unsigned*)chm_s)[i] = ((const unsigned*)g_chmin[b])[i];
    }
    __syncthreads();
    if (tid < NC) {
        int run = 0, mypref = 0;
        unsigned mn = 0xFF800000u;
        for (int h2 = 0; h2 < 32; h2++) {
            if (h2 == ch) mypref = run;
            run += hist_s[h2][tid];
            mn = min(mn, chm_s[h2][tid]);
        }
        pref_s[tid] = mypref;
        cnt_s[tid] = run;
        small_s[tid] = fminf(funkey(mn), -10.0f) * INV_T;
    }

    const int c = cls[row];
    unsigned match = __match_any_sync(0xFFFFFFFFu, c);
    int lr = __popc(match & ((1u << lane) - 1u));
#pragma unroll
    for (int c2 = 0; c2 < NC; c2++) {
        unsigned bal = __ballot_sync(0xFFFFFFFFu, c == c2);
        if (lane == c2) wcnt[w][c2] = __popc(bal);
    }
    __syncthreads();
    for (int w2 = 0; w2 < w; w2++) lr += wcnt[w2][c];
    int classpref = 0;
    for (int c2 = 0; c2 < c; c2++) classpref += cnt_s[c2];
    const int opos = b * NP + classpref + pref_s[c] + lr;

    const float pos_n = g_pos[row];
    const float M = g_m[row], S = g_s[row];
    const float lneg = (S > 0.f) ? (M * LN2F + logf(S)) : NEGINF;

    const int   npad = cnt_s[c] - 1;
    const float pad  = (npad > 0) ? (logf((float)npad) + small_s[c]) : NEGINF;

    const float Mx  = fmaxf(pos_n, fmaxf(lneg, pad));
    const float sum = expf(pos_n - Mx) + expf(lneg - Mx) + expf(pad - Mx);
    out[opos] = Mx + logf(sum) - pos_n;
}

/* ============================================================================ */
extern "C" void kernel_launch(void* const* d_in, const int* in_sizes, int n_in,
                              void* d_out, int out_size)
{
    const float* src = (const float*)d_in[0];
    const float* tgt = (const float*)d_in[1];
    const int*   cls = (const int*)d_in[2];
    float*       out = (float*)d_out;

    cudaFuncSetAttribute(nce_gemm_mma, cudaFuncAttributeMaxDynamicSharedMemorySize, SMEM_BYTES);

    cvt_pos<<<NROWS / 8, 256>>>(src, tgt);
    nce_gemm_mma<<<dim3(32, NBATCH), 512, SMEM_BYTES>>>(src, cls);
    nce_final<<<dim3(32, NBATCH), 128>>>(cls, out);
}